// round 17
// baseline (speedup 1.0000x reference)
#include <cuda_runtime.h>
#include <cuda_fp16.h>
#include <math.h>
#include <stdint.h>

// ---------------------------------------------------------------------------
// Scratch (device globals; allocation-free). ~40 MB total.
// ---------------------------------------------------------------------------
__device__ __align__(16) __half g_W[4194304];    // all 4 layers, packed (fp16)
__device__ __align__(16) __half g_act1[4194304]; // (512,16,16,32) NHWC fp16
__device__ __align__(16) __half g_act2[2097152]; // (512,8,8,64)   NHWC fp16
__device__ __align__(16) __half g_act3[1048576]; // (512,4,4,128)  NHWC fp16
__device__ __align__(16) __half g_act4[262144];  // (512,2,2,128)  NHWC fp16
__device__ float g_part[4194304];     // split-K fp32 partials (16 MB)
__device__ float g_bsum[32768], g_bsum2[32768];  // 256 blocks x 128 ch partials
__device__ float g_bnS1[64],  g_bnT1[64];
__device__ float g_bnS2[128], g_bnT2[128];
__device__ float g_bnS3[128], g_bnT3[128];

// Packed W offsets (elements): L1 32*384, L2 64*4096, L3 128*8192, L4 128*16384
#define WOFF1 0
#define WOFF2 12288
#define WOFF3 274432
#define WOFF4 1323008

// ---------------------------------------------------------------------------
// Helpers
// ---------------------------------------------------------------------------
__device__ __forceinline__ uint32_t smem_u32(const void* p) {
    uint32_t a;
    asm("{ .reg .u64 t; cvta.to.shared.u64 t, %1; cvt.u32.u64 %0, t; }"
        : "=r"(a) : "l"(p));
    return a;
}
__device__ __forceinline__ uint32_t sw128(uint32_t off) {
    return off ^ ((off >> 3) & 0x70);
}
__device__ __forceinline__ void sts128(uint32_t addr, uint32_t a, uint32_t b,
                                       uint32_t c, uint32_t d) {
    asm volatile("st.shared.v4.b32 [%0], {%1, %2, %3, %4};"
                 :: "r"(addr), "r"(a), "r"(b), "r"(c), "r"(d) : "memory");
}
__device__ __forceinline__ void cp16(uint32_t dst, const void* src) {
    asm volatile("cp.async.cg.shared.global [%0], [%1], 16;"
                 :: "r"(dst), "l"(src) : "memory");
}
__device__ __forceinline__ void cp_commit() {
    asm volatile("cp.async.commit_group;" ::: "memory");
}
template <int N>
__device__ __forceinline__ void cp_wait() {
    asm volatile("cp.async.wait_group %0;" :: "n"(N) : "memory");
}
__device__ __forceinline__ void ldsm_x4(uint32_t* r, uint32_t addr) {
    asm volatile("ldmatrix.sync.aligned.m8n8.x4.shared.b16 {%0,%1,%2,%3}, [%4];"
                 : "=r"(r[0]), "=r"(r[1]), "=r"(r[2]), "=r"(r[3]) : "r"(addr));
}
__device__ __forceinline__ void mma16816(float* c, const uint32_t* a, const uint32_t* b) {
    asm volatile(
        "mma.sync.aligned.m16n8k16.row.col.f32.f16.f16.f32 "
        "{%0,%1,%2,%3}, {%4,%5,%6,%7}, {%8,%9}, {%0,%1,%2,%3};"
        : "+f"(c[0]), "+f"(c[1]), "+f"(c[2]), "+f"(c[3])
        : "r"(a[0]), "r"(a[1]), "r"(a[2]), "r"(a[3]), "r"(b[0]), "r"(b[1]));
}
__device__ __forceinline__ uint32_t h2pack(float a, float b) {
    __half2 h = __floats2half2_rn(a, b);
    return *reinterpret_cast<uint32_t*>(&h);
}
__device__ __forceinline__ float ldval(const float* p, int off) { return p[off]; }
__device__ __forceinline__ float ldval(const __half* p, int off) {
    return __half2float(p[off]);
}
__device__ __forceinline__ void storepair(float* dst, float a, float b) {
    *(float2*)dst = make_float2(a, b);
}
__device__ __forceinline__ void storepair(__half* dst, float a, float b) {
    *(__half2*)dst = __floats2half2_rn(a, b);
}

// ---------------------------------------------------------------------------
// Closed-form quadratic B-spline (grid_size=3, order=2, uniform knots).
// ---------------------------------------------------------------------------
__device__ __forceinline__ void spline5(float x, float* bo) {
    float u = (x + 7.0f / 3.0f) * 1.5f;
    float fi = floorf(u);
    int i = (int)fi;
    float t = u - fi;
    float omt = 1.0f - t;
    float q0 = 0.5f * omt * omt;
    float q2 = 0.5f * t * t;
    float q1 = 1.0f - q0 - q2;
#pragma unroll
    for (int j = 0; j < 5; j++) {
        float v = 0.0f;
        v = (j == i - 2) ? q0 : v;
        v = (j == i - 1) ? q1 : v;
        v = (j == i)     ? q2 : v;
        bo[j] = v;
    }
}

// ---------------------------------------------------------------------------
// Fused weight build for all 4 layers (one launch).
// ---------------------------------------------------------------------------
struct BArgs {
    const float *bw, *sw, *sc;
    int F, O, Kpad, corder, Cin, woff, count;
};
__device__ __forceinline__ void build_one(const BArgs& a, int idx, __half* w) {
    int o = idx / a.Kpad;
    int k = idx - o * a.Kpad;
    int f = k >> 3;
    int t = k & 7;
    int fsrc = f;
    if (a.corder) {
        int r = f / a.Cin;
        int c = f - r * a.Cin;
        fsrc = c * 16 + r;
    }
    float val = 0.0f;
    if (t == 0)      val = a.bw[o * a.F + fsrc];
    else if (t <= 5) val = a.sw[(o * a.F + fsrc) * 5 + (t - 1)] * a.sc[o * a.F + fsrc];
    w[a.woff + idx] = __float2half_rn(val);
}
__global__ void build_all_kernel(BArgs a0, BArgs a1, BArgs a2, BArgs a3,
                                 __half* __restrict__ w) {
    int idx = blockIdx.x * blockDim.x + threadIdx.x;
    if (idx < a0.count) { build_one(a0, idx, w); return; }
    idx -= a0.count;
    if (idx < a1.count) { build_one(a1, idx, w); return; }
    idx -= a1.count;
    if (idx < a2.count) { build_one(a2, idx, w); return; }
    idx -= a2.count;
    if (idx < a3.count) { build_one(a3, idx, w); }
}

// ---------------------------------------------------------------------------
// Fused KAN-conv GEMM on mma.sync (fp16 A, fp16 W single-term, fp32 accum).
// Identical to the 337us-passing round-16 kernel.
// ---------------------------------------------------------------------------
template <int BN, typename SrcT, typename OutT>
__global__ __launch_bounds__(256, (BN >= 128 ? 2 : 3))
void kan_mma_kernel(const SrcT* __restrict__ src,
                    const __half* __restrict__ W,
                    OutT* __restrict__ C,
                    const float* __restrict__ bns,
                    const float* __restrict__ bnt,
                    int M, int O, int Cin, int Hin, int hs, int nchw,
                    int fCount, int Kpad, int corder, int cinShift) {
    constexpr int BM = 128;
    constexpr int BF = 8;
    constexpr int WN = BN / 2;
    constexpr int NA = WN / 8;
    constexpr int NPAIR = NA / 2;
    constexpr int A_BYTES = BM * 128;
    constexpr int B_BYTES = BN * 128;
    constexpr int BUF_STRIDE = A_BYTES + B_BYTES;
    constexpr int BITER = (BN * 8) / 256;

    extern __shared__ char dynsmem[];
    uintptr_t tbase = ((uintptr_t)dynsmem + 1023) & ~(uintptr_t)1023;
    const uint32_t base0 = smem_u32((void*)tbase);

    const int tid = threadIdx.x;
    const int lane = tid & 31;
    const int wid = tid >> 5;
    const int warp_m = wid & 3;
    const int warp_n = wid >> 2;

    const int z = blockIdx.z;
    const int fBase = z * fCount;
    const int row0 = blockIdx.x * BM;
    const int col0 = blockIdx.y * BN;
    OutT* Cz = C + z * M * O;

    float acc[2][NA][4];
#pragma unroll
    for (int i = 0; i < 2; i++)
#pragma unroll
        for (int j = 0; j < NA; j++)
#pragma unroll
            for (int q = 0; q < 4; q++) acc[i][j][q] = 0.0f;

    const int Hout = 1 << hs;
    const int hwMask = (Hout * Hout) - 1;
    const int hwShift = 2 * hs;
    const int NC = fCount / BF;

    const uint32_t aRowOff = (uint32_t)(lane & 15) * 128 + ((uint32_t)(lane >> 4) << 4);
    const uint32_t bRowOff = ((uint32_t)((lane & 7) + ((lane >> 4) << 3))) * 128 +
                             (((uint32_t)(lane >> 3) & 1u) << 4);
    uint32_t aOffSw[2], bOffSw[NPAIR];
#pragma unroll
    for (int am = 0; am < 2; am++)
        aOffSw[am] = sw128((uint32_t)((warp_m * 32 + am * 16) * 128) + aRowOff);
#pragma unroll
    for (int pr = 0; pr < NPAIR; pr++)
        bOffSw[pr] = sw128((uint32_t)((warp_n * WN + pr * 16) * 128) + bRowOff);

    const int c_off = tid & 7;

    uint32_t swA[4];
#pragma unroll
    for (int it = 0; it < 4; it++) {
        int mLocal, fl;
        if (corder) { mLocal = (tid >> 3) + it * 32; fl = c_off; }
        else        { int l = tid + it * 256; mLocal = l & (BM - 1); fl = l >> 7; }
        swA[it] = sw128((uint32_t)(mLocal * 128 + fl * 16));
    }
    uint32_t swB[BITER];
    int gidxB[BITER];
#pragma unroll
    for (int it = 0; it < BITER; it++) {
        const int l = tid + it * 256;
        const int rown = l >> 3;
        const int cg = l & 7;
        swB[it] = sw128((uint32_t)(rown * 128 + cg * 16));
        gidxB[it] = (col0 + rown) * Kpad + fBase * 8 + cg * 8;
    }

    float pv[4];
    int poff[4];
    unsigned pvmask = 0;
    int pc = 0;

    auto prefA = [&](int cc) {
        if (corder) {
            const int fc = fBase + cc * BF;
            if ((fc & (Cin - 1)) == 0) {
                const int r = fc >> cinShift;
                pc = c_off;
                const int wi = r >> 2, wj = r & 3;
                pvmask = 0;
#pragma unroll
                for (int it = 0; it < 4; it++) {
                    const int m = row0 + (tid >> 3) + it * 32;
                    const int p = m & hwMask;
                    const int b = m >> hwShift;
                    const int ho = p >> hs, wo = p & (Hout - 1);
                    const int ih = 2 * ho + wi - 1;
                    const int iw = 2 * wo + wj - 1;
                    poff[it] = (((b * Hin + ih) * Hin + iw) << cinShift) + pc;
                    if ((unsigned)ih < (unsigned)Hin && (unsigned)iw < (unsigned)Hin)
                        pvmask |= 1u << it;
                }
            } else {
                pc += BF;
#pragma unroll
                for (int it = 0; it < 4; it++) poff[it] += BF;
            }
            float s = 1.0f, t = 0.0f;
            if (bns) { s = bns[pc]; t = bnt[pc]; }
#pragma unroll
            for (int it = 0; it < 4; it++) {
                float v = 0.0f;
                if ((pvmask >> it) & 1u) {
                    v = ldval(src, poff[it]);
                    v = fmaf(v, s, t);
                }
                pv[it] = v;
            }
        } else {
#pragma unroll
            for (int it = 0; it < 4; it++) {
                const int l = tid + it * 256;
                const int mLocal = l & (BM - 1);
                const int fl = l >> 7;
                const int m = row0 + mLocal;
                const int f = fBase + cc * BF + fl;
                const int p = m & hwMask;
                const int b = m >> hwShift;
                const int ho = p >> hs, wo = p & (Hout - 1);
                const int c = f >> 4;
                const int r = f & 15;
                const int ih = 2 * ho + (r >> 2) - 1;
                const int iw = 2 * wo + (r & 3) - 1;
                float v = 0.0f;
                if ((unsigned)ih < (unsigned)Hin && (unsigned)iw < (unsigned)Hin) {
                    int off = nchw
                        ? (((b * Cin + c) * Hin + ih) * Hin + iw)
                        : (((b * Hin + ih) * Hin + iw) * Cin + c);
                    v = ldval(src, off);
                    if (bns) v = fmaf(v, bns[c], bnt[c]);
                }
                pv[it] = v;
            }
        }
    };
    auto issueB = [&](int cc) {
        const int buf = cc & 1;
        const uint32_t BH0 = base0 + buf * BUF_STRIDE + A_BYTES;
        const int kadd = cc * BF * 8;
#pragma unroll
        for (int it = 0; it < BITER; it++)
            cp16(BH0 + swB[it], W + gidxB[it] + kadd);
        cp_commit();
    };

    issueB(0);
    prefA(0);

    for (int cch = 0; cch < NC; cch++) {
        const int buf = cch & 1;
        const uint32_t A0 = base0 + buf * BUF_STRIDE;
        const uint32_t BH0 = A0 + A_BYTES;

#pragma unroll
        for (int it = 0; it < 4; it++) {
            const float v = pv[it];
            float vals[6];
            vals[0] = fmaxf(v, 0.0f);
            spline5(v, &vals[1]);
            sts128(A0 + swA[it], h2pack(vals[0], vals[1]), h2pack(vals[2], vals[3]),
                   h2pack(vals[4], vals[5]), 0u);
        }
        cp_wait<0>();
        __syncthreads();

        if (cch + 1 < NC) {
            issueB(cch + 1);
            prefA(cch + 1);
        }

#pragma unroll
        for (int ks = 0; ks < 4; ks++) {
            const uint32_t kb = (uint32_t)(ks * 32);
            uint32_t ah[2][4];
#pragma unroll
            for (int am = 0; am < 2; am++)
                ldsm_x4(ah[am], A0 + (aOffSw[am] ^ kb));
            uint32_t bh[NA][2];
#pragma unroll
            for (int pr = 0; pr < NPAIR; pr++) {
                uint32_t t[4];
                ldsm_x4(t, BH0 + (bOffSw[pr] ^ kb));
                bh[2 * pr][0] = t[0]; bh[2 * pr][1] = t[1];
                bh[2 * pr + 1][0] = t[2]; bh[2 * pr + 1][1] = t[3];
            }
#pragma unroll
            for (int am = 0; am < 2; am++)
#pragma unroll
                for (int an = 0; an < NA; an++)
                    mma16816(acc[am][an], ah[am], bh[an]);
        }
    }

#pragma unroll
    for (int am = 0; am < 2; am++) {
        const int rr = row0 + warp_m * 32 + am * 16 + (lane >> 2);
#pragma unroll
        for (int an = 0; an < NA; an++) {
            const int cc = col0 + warp_n * WN + an * 8 + (lane & 3) * 2;
            storepair(&Cz[rr * O + cc], acc[am][an][0], acc[am][an][1]);
            storepair(&Cz[(rr + 8) * O + cc], acc[am][an][2], acc[am][an][3]);
        }
    }
}

// ---------------------------------------------------------------------------
// Fused split-K reduce + BN-stat partials. Writes fp16 act; accumulates
// per-channel sum/sum^2 (fixed channel per slot since C | 1024 and the
// grid stride is a multiple of C). Deterministic fixed-order sums.
// ---------------------------------------------------------------------------
__global__ void reduce_stats_kernel(const float* __restrict__ part,
                                    __half* __restrict__ out,
                                    float* __restrict__ bsum,
                                    float* __restrict__ bsum2,
                                    int MN, int S, int C, int nBlocks) {
    const int tid = threadIdx.x;
    const int stride = nBlocks * 1024;
    float a0 = 0, a1 = 0, a2 = 0, a3 = 0;
    float q0 = 0, q1 = 0, q2 = 0, q3 = 0;
    for (int base = blockIdx.x * 1024 + tid * 4; base < MN; base += stride) {
        float4 a = make_float4(0.f, 0.f, 0.f, 0.f);
        for (int s = 0; s < S; s++) {
            const float4 p = *(const float4*)&part[(size_t)s * MN + base];
            a.x += p.x; a.y += p.y; a.z += p.z; a.w += p.w;
        }
        *(__half2*)&out[base]     = __floats2half2_rn(a.x, a.y);
        *(__half2*)&out[base + 2] = __floats2half2_rn(a.z, a.w);
        a0 += a.x; q0 += a.x * a.x;
        a1 += a.y; q1 += a.y * a.y;
        a2 += a.z; q2 += a.z * a.z;
        a3 += a.w; q3 += a.w * a.w;
    }
    __shared__ float sh[1024], sh2[1024];
    sh[tid * 4 + 0] = a0; sh2[tid * 4 + 0] = q0;
    sh[tid * 4 + 1] = a1; sh2[tid * 4 + 1] = q1;
    sh[tid * 4 + 2] = a2; sh2[tid * 4 + 2] = q2;
    sh[tid * 4 + 3] = a3; sh2[tid * 4 + 3] = q3;
    __syncthreads();
    // 1024 -> 256 (slots tid, tid+256, tid+512, tid+768 share channel: 256%C==0)
    sh[tid]  = sh[tid] + sh[tid + 256] + sh[tid + 512] + sh[tid + 768];
    sh2[tid] = sh2[tid] + sh2[tid + 256] + sh2[tid + 512] + sh2[tid + 768];
    __syncthreads();
    for (int off = 128; off >= C; off >>= 1) {
        if (tid < off) { sh[tid] += sh[tid + off]; sh2[tid] += sh2[tid + off]; }
        __syncthreads();
    }
    if (tid < C) {
        bsum[blockIdx.x * C + tid]  = sh[tid];
        bsum2[blockIdx.x * C + tid] = sh2[tid];
    }
}

__global__ void finalize_stats_kernel(const float* __restrict__ bsum,
                                      const float* __restrict__ bsum2,
                                      const float* __restrict__ gamma,
                                      const float* __restrict__ beta,
                                      float* __restrict__ s_out,
                                      float* __restrict__ t_out,
                                      int nBlocks, int C, int n) {
    int c = threadIdx.x;
    if (c >= C) return;
    double s = 0, q = 0;
    for (int b = 0; b < nBlocks; b++) {
        s += bsum[b * C + c];
        q += bsum2[b * C + c];
    }
    double mean = s / n;
    double var = q / n - mean * mean;
    double sv = (double)gamma[c] * rsqrt(var + 1e-5);
    s_out[c] = (float)sv;
    t_out[c] = (float)((double)beta[c] - mean * sv);
}

// ---------------------------------------------------------------------------
// Head: BN3 affine + avgpool(2x2) + fc(128->1) + sigmoid.
// ---------------------------------------------------------------------------
__global__ void head_kernel(const __half* __restrict__ act4,
                            const float* __restrict__ s,
                            const float* __restrict__ t,
                            const float* __restrict__ fcw,
                            const float* __restrict__ fcb,
                            float* __restrict__ out) {
    int b = blockIdx.x;
    int c = threadIdx.x;
    const __half* p = act4 + b * 4 * 128;
    float mval = 0.25f * (__half2float(p[c]) + __half2float(p[128 + c]) +
                          __half2float(p[256 + c]) + __half2float(p[384 + c]));
    float v = (s[c] * mval + t[c]) * fcw[c];
    __shared__ float sh[128];
    sh[c] = v;
    __syncthreads();
    for (int o = 64; o > 0; o >>= 1) {
        if (c < o) sh[c] += sh[c + o];
        __syncthreads();
    }
    if (c == 0) {
        float zv = sh[0] + fcb[0];
        out[b] = 1.0f / (1.0f + expf(-zv));
    }
}

// ---------------------------------------------------------------------------
// Launch
// ---------------------------------------------------------------------------
extern "C" void kernel_launch(void* const* d_in, const int* in_sizes, int n_in,
                              void* d_out, int out_size) {
    const float* x   = (const float*)d_in[0];
    const float* bw1 = (const float*)d_in[1];
    const float* sw1 = (const float*)d_in[2];
    const float* sc1 = (const float*)d_in[3];
    const float* bw2 = (const float*)d_in[4];
    const float* sw2 = (const float*)d_in[5];
    const float* sc2 = (const float*)d_in[6];
    const float* bw3 = (const float*)d_in[7];
    const float* sw3 = (const float*)d_in[8];
    const float* sc3 = (const float*)d_in[9];
    const float* bw4 = (const float*)d_in[10];
    const float* sw4 = (const float*)d_in[11];
    const float* sc4 = (const float*)d_in[12];
    const float* g1  = (const float*)d_in[13];
    const float* b1  = (const float*)d_in[14];
    const float* g2  = (const float*)d_in[15];
    const float* b2  = (const float*)d_in[16];
    const float* g3  = (const float*)d_in[17];
    const float* b3  = (const float*)d_in[18];
    const float* fcw = (const float*)d_in[19];
    const float* fcb = (const float*)d_in[20];
    float* out = (float*)d_out;

    __half *w, *act1, *act2, *act3, *act4;
    float *part, *bsum, *bsum2;
    float *s1, *t1, *s2, *t2, *s3, *t3;
    cudaGetSymbolAddress((void**)&w, g_W);
    cudaGetSymbolAddress((void**)&act1, g_act1);
    cudaGetSymbolAddress((void**)&act2, g_act2);
    cudaGetSymbolAddress((void**)&act3, g_act3);
    cudaGetSymbolAddress((void**)&act4, g_act4);
    cudaGetSymbolAddress((void**)&part, g_part);
    cudaGetSymbolAddress((void**)&bsum, g_bsum);
    cudaGetSymbolAddress((void**)&bsum2, g_bsum2);
    cudaGetSymbolAddress((void**)&s1, g_bnS1);
    cudaGetSymbolAddress((void**)&t1, g_bnT1);
    cudaGetSymbolAddress((void**)&s2, g_bnS2);
    cudaGetSymbolAddress((void**)&t2, g_bnT2);
    cudaGetSymbolAddress((void**)&s3, g_bnS3);
    cudaGetSymbolAddress((void**)&t3, g_bnT3);

    const int RB = 256;  // reduce_stats grid
    const int SMEM32  = 2 * (16384 + 32 * 128) + 1024;
    const int SMEM64  = 2 * (16384 + 64 * 128) + 1024;
    const int SMEM128 = 2 * (16384 + 128 * 128) + 1024;
    cudaFuncSetAttribute(kan_mma_kernel<32, float, __half>,
                         cudaFuncAttributeMaxDynamicSharedMemorySize, SMEM32);
    cudaFuncSetAttribute(kan_mma_kernel<64, __half, float>,
                         cudaFuncAttributeMaxDynamicSharedMemorySize, SMEM64);
    cudaFuncSetAttribute(kan_mma_kernel<128, __half, float>,
                         cudaFuncAttributeMaxDynamicSharedMemorySize, SMEM128);

    // ---- Fused weight build (all layers, one launch) ------------------------
    {
        BArgs a1 = {bw1, sw1, sc1, 48,   32, 384,   0, 3,   WOFF1, 32 * 384};
        BArgs a2 = {bw2, sw2, sc2, 512,  64, 4096,  1, 32,  WOFF2, 64 * 4096};
        BArgs a3 = {bw3, sw3, sc3, 1024, 128, 8192, 1, 64,  WOFF3, 128 * 8192};
        BArgs a4 = {bw4, sw4, sc4, 2048, 128, 16384, 1, 128, WOFF4, 128 * 16384};
        int total = a1.count + a2.count + a3.count + a4.count;
        build_all_kernel<<<(total + 255) / 256, 256>>>(a1, a2, a3, a4, w);
    }
    // ---- Layer 1: (512,3,32,32) NCHW fp32 -> act1 fp16 directly -------------
    {
        const int F = 48, O = 32, M = 512 * 16 * 16, Kpad = 8 * F;
        kan_mma_kernel<32, float, __half><<<dim3(M / 128, 1, 1), 256, SMEM32>>>(
            x, w + WOFF1, act1, nullptr, nullptr,
            M, O, 3, 32, 4, 1, F, Kpad, 0, 0);
    }
    // ---- Layer 2: -> act2 fp16 via split2 + fused BN1 stats -----------------
    {
        const int F = 512, O = 64, M = 512 * 8 * 8, Kpad = 8 * F;
        const int SPLIT = 2;
        kan_mma_kernel<64, __half, float><<<dim3(M / 128, 1, SPLIT), 256, SMEM64>>>(
            act1, w + WOFF2, part, nullptr, nullptr,
            M, O, 32, 16, 3, 0, F / SPLIT, Kpad, 1, 5);
        reduce_stats_kernel<<<RB, 256>>>(part, act2, bsum, bsum2, M * O, SPLIT, O, RB);
        finalize_stats_kernel<<<1, O>>>(bsum, bsum2, g1, b1, s1, t1, RB, O, M);
    }
    // ---- Layer 3: BN1 fused -> act3 fp16, BN=128 tile, split4 + BN2 stats ---
    {
        const int F = 1024, O = 128, M = 512 * 4 * 4, Kpad = 8 * F;
        const int SPLIT = 4;
        kan_mma_kernel<128, __half, float><<<dim3(M / 128, 1, SPLIT), 256, SMEM128>>>(
            act2, w + WOFF3, part, s1, t1,
            M, O, 64, 8, 2, 0, F / SPLIT, Kpad, 1, 6);
        reduce_stats_kernel<<<RB, 256>>>(part, act3, bsum, bsum2, M * O, SPLIT, O, RB);
        finalize_stats_kernel<<<1, O>>>(bsum, bsum2, g2, b2, s2, t2, RB, O, M);
    }
    // ---- Layer 4: BN2 fused -> act4 fp16, BN=128 tile, split8 + BN3 stats ---
    {
        const int F = 2048, O = 128, M = 512 * 2 * 2, Kpad = 8 * F;
        const int SPLIT = 8;
        kan_mma_kernel<128, __half, float><<<dim3(M / 128, 1, SPLIT), 256, SMEM128>>>(
            act3, w + WOFF4, part, s2, t2,
            M, O, 128, 4, 1, 0, F / SPLIT, Kpad, 1, 7);
        reduce_stats_kernel<<<RB, 256>>>(part, act4, bsum, bsum2, M * O, SPLIT, O, RB);
        finalize_stats_kernel<<<1, O>>>(bsum, bsum2, g3, b3, s3, t3, RB, O, M);
    }
    // ---- Head --------------------------------------------------------------
    head_kernel<<<512, 128>>>(act4, s3, t3, fcw, fcb, out);
}